// round 7
// baseline (speedup 1.0000x reference)
#include <cuda_runtime.h>
#include <cstdint>

// C4TransformerVM: exact 4-byte ripple-carry add over one-hot byte encodings.
// softmax(temp=100) over integer logit gaps (scaled by 100) makes every
// intermediate one-hot to ~exp(-100) ~ 3.6e-44 in fp32 -> decode (argmax),
// uint32 add (final carry discarded per reference), re-encode one-hot.
//
// History:
//  R3 fused 67.6us @ DRAM 69% (regs=40, MLP~6).
//  R4 split kernels: regression (pure-write stream only 25% DRAM).
//  R5 + launch_bounds(256,3): 63.8us @ 77.6% (MLP=16).
//  R6 + zero-store overlap / owner-lane patch: 63.5us @ 79.2%.
//  R7: persistent grid-stride (444 CTAs = 148 SMs x 3). Removes the 9.2-wave
//      CTA relaunch ramp; steady-state warps re-issue the next tile's loads
//      ~50 cycles after the previous REDUX, so the read pipe never drains.

__device__ __forceinline__ uint32_t scan8_mask(float4 v0, float4 v1, int base, int sh) {
    uint32_t idx = 0;
    if (v0.x > 0.5f) idx = (uint32_t)(base + 0);
    if (v0.y > 0.5f) idx = (uint32_t)(base + 1);
    if (v0.z > 0.5f) idx = (uint32_t)(base + 2);
    if (v0.w > 0.5f) idx = (uint32_t)(base + 3);
    if (v1.x > 0.5f) idx = (uint32_t)(base + 4);
    if (v1.y > 0.5f) idx = (uint32_t)(base + 5);
    if (v1.z > 0.5f) idx = (uint32_t)(base + 6);
    if (v1.w > 0.5f) idx = (uint32_t)(base + 7);
    return idx << sh;
}

__global__ __launch_bounds__(256, 3) void neural_alu_add_kernel(
    const float* __restrict__ a,
    const float* __restrict__ b,
    float* __restrict__ out,
    int N)
{
    const int lane = threadIdx.x & 31;
    const int warp0 = (blockIdx.x * blockDim.x + threadIdx.x) >> 5;
    const int nwarps = (gridDim.x * blockDim.x) >> 5;
    const int base = lane * 8;

#pragma unroll 1
    for (int n = warp0; n < N; n += nwarps) {
        // ---- Phase 1: issue all 16 float4 loads (MLP = 16).
        float4 va[8], vb[8];
#pragma unroll
        for (int i = 0; i < 4; i++) {
            const float4* ra = reinterpret_cast<const float4*>(a + ((size_t)i * N + n) * 256);
            const float4* rb = reinterpret_cast<const float4*>(b + ((size_t)i * N + n) * 256);
            va[2 * i]     = __ldcs(ra + lane * 2);
            va[2 * i + 1] = __ldcs(ra + lane * 2 + 1);
            vb[2 * i]     = __ldcs(rb + lane * 2);
            vb[2 * i + 1] = __ldcs(rb + lane * 2 + 1);
        }

        // ---- Phase 2: store zeros to all 4 output rows (independent of the
        // loads; drains while reads are in flight).
        const float4 z = make_float4(0.f, 0.f, 0.f, 0.f);
#pragma unroll
        for (int i = 0; i < 4; i++) {
            float4* ro = reinterpret_cast<float4*>(out + ((size_t)i * N + n) * 256);
            __stcs(ro + lane * 2,     z);
            __stcs(ro + lane * 2 + 1, z);
        }

        // ---- Phase 3: decode. Pack byte-i index into bits [8i,8i+8); at
        // most one lane nonzero per byte (hot index 0 => all-zero, also
        // correct), so one OR-reduction per operand rebuilds the 32-bit word.
        uint32_t Ap = 0, Bp = 0;
#pragma unroll
        for (int i = 0; i < 4; i++) {
            Ap |= scan8_mask(va[2 * i], va[2 * i + 1], base, 8 * i);
            Bp |= scan8_mask(vb[2 * i], vb[2 * i + 1], base, 8 * i);
        }
        const uint32_t A = __reduce_or_sync(0xffffffffu, Ap);
        const uint32_t B = __reduce_or_sync(0xffffffffu, Bp);

        const uint32_t S = A + B;   // carry out of byte 3 discarded

        // ---- Phase 4: owning lane patches the hot element of each row.
        // Same thread + same address as its zero store -> program order
        // guarantees the 1.0 lands last.
#pragma unroll
        for (int i = 0; i < 4; i++) {
            const int r = (int)((S >> (8 * i)) & 255u);
            if ((r >> 3) == lane) {
                __stcs(out + ((size_t)i * N + n) * 256 + r, 1.0f);
            }
        }
    }
}

extern "C" void kernel_launch(void* const* d_in, const int* in_sizes, int n_in,
                              void* d_out, int out_size) {
    const float* a = (const float*)d_in[0];   // [4, N, 256] one-hot
    const float* b = (const float*)d_in[1];   // [4, N, 256] one-hot
    float* out = (float*)d_out;               // [4, N, 256]
    const int N = in_sizes[0] / (4 * 256);

    const int threads = 256;                  // 8 warps/block
    const int blocks = 148 * 3;               // persistent: 3 CTAs per SM
    neural_alu_add_kernel<<<blocks, threads>>>(a, b, out, N);
}

// round 8
// speedup vs baseline: 1.1308x; 1.1308x over previous
#include <cuda_runtime.h>
#include <cstdint>

// C4TransformerVM: exact 4-byte ripple-carry add over one-hot byte encodings.
// softmax(temp=100) over integer logit gaps (scaled by 100) makes every
// intermediate one-hot to ~exp(-100) ~ 3.6e-44 in fp32 -> decode (argmax),
// uint32 add (final carry discarded per reference), re-encode one-hot.
//
// History:
//  R3 fused 67.6us @ DRAM 69% (regs=40, MLP~6).
//  R4 split kernels: regression (pure-write stream only 25% DRAM).
//  R5 + launch_bounds(256,3): 63.8us @ 77.6% (MLP=16).
//  R6 + zero-store overlap / owner-lane patch: 63.5us @ 79.2%.  <- best
//  R7 persistent grid-stride: REGRESSION (70.6%) — loop serialized tiles
//     within a warp and lockstepped the resident warps. CTA churn IS the
//     cross-tile pipeline; keep it.
//  R8: R6 body, but 64-thread CTAs x 12/SM (same 24 warps/SM, same regs/MLP)
//      -> 4x finer CTA retirement/back-fill granularity, smoother load issue
//      across the 9.2 waves.

__device__ __forceinline__ uint32_t scan8_mask(float4 v0, float4 v1, int base, int sh) {
    uint32_t idx = 0;
    if (v0.x > 0.5f) idx = (uint32_t)(base + 0);
    if (v0.y > 0.5f) idx = (uint32_t)(base + 1);
    if (v0.z > 0.5f) idx = (uint32_t)(base + 2);
    if (v0.w > 0.5f) idx = (uint32_t)(base + 3);
    if (v1.x > 0.5f) idx = (uint32_t)(base + 4);
    if (v1.y > 0.5f) idx = (uint32_t)(base + 5);
    if (v1.z > 0.5f) idx = (uint32_t)(base + 6);
    if (v1.w > 0.5f) idx = (uint32_t)(base + 7);
    return idx << sh;
}

__global__ __launch_bounds__(64, 12) void neural_alu_add_kernel(
    const float* __restrict__ a,
    const float* __restrict__ b,
    float* __restrict__ out,
    int N)
{
    const int warp_id = (blockIdx.x * blockDim.x + threadIdx.x) >> 5;
    const int lane = threadIdx.x & 31;
    if (warp_id >= N) return;
    const size_t n = (size_t)warp_id;
    const int base = lane * 8;

    // ---- Phase 1: issue all 16 float4 loads (MLP = 16).
    float4 va[8], vb[8];
#pragma unroll
    for (int i = 0; i < 4; i++) {
        const float4* ra = reinterpret_cast<const float4*>(a + ((size_t)i * N + n) * 256);
        const float4* rb = reinterpret_cast<const float4*>(b + ((size_t)i * N + n) * 256);
        va[2 * i]     = __ldcs(ra + lane * 2);
        va[2 * i + 1] = __ldcs(ra + lane * 2 + 1);
        vb[2 * i]     = __ldcs(rb + lane * 2);
        vb[2 * i + 1] = __ldcs(rb + lane * 2 + 1);
    }

    // ---- Phase 2: store zeros to all 4 output rows. Independent of the
    // loads -> drains while the reads are still in flight.
    const float4 z = make_float4(0.f, 0.f, 0.f, 0.f);
#pragma unroll
    for (int i = 0; i < 4; i++) {
        float4* ro = reinterpret_cast<float4*>(out + ((size_t)i * N + n) * 256);
        __stcs(ro + lane * 2,     z);
        __stcs(ro + lane * 2 + 1, z);
    }

    // ---- Phase 3: decode. Pack byte-i index into bits [8i,8i+8); at most
    // one lane nonzero per byte (hot index 0 => all-zero, also correct), so
    // one OR-reduction per operand reconstructs the 32-bit word.
    uint32_t Ap = 0, Bp = 0;
#pragma unroll
    for (int i = 0; i < 4; i++) {
        Ap |= scan8_mask(va[2 * i], va[2 * i + 1], base, 8 * i);
        Bp |= scan8_mask(vb[2 * i], vb[2 * i + 1], base, 8 * i);
    }
    const uint32_t A = __reduce_or_sync(0xffffffffu, Ap);
    const uint32_t B = __reduce_or_sync(0xffffffffu, Bp);

    const uint32_t S = A + B;   // carry out of byte 3 discarded

    // ---- Phase 4: owning lane patches the hot element of each row. Same
    // thread + same address as its zero store -> program order guarantees
    // the 1.0 lands last.
#pragma unroll
    for (int i = 0; i < 4; i++) {
        const int r = (int)((S >> (8 * i)) & 255u);
        if ((r >> 3) == lane) {
            __stcs(out + ((size_t)i * N + n) * 256 + r, 1.0f);
        }
    }
}

extern "C" void kernel_launch(void* const* d_in, const int* in_sizes, int n_in,
                              void* d_out, int out_size) {
    const float* a = (const float*)d_in[0];   // [4, N, 256] one-hot
    const float* b = (const float*)d_in[1];   // [4, N, 256] one-hot
    float* out = (float*)d_out;               // [4, N, 256]
    const int N = in_sizes[0] / (4 * 256);

    const int threads = 64;                   // 2 warps/block, 1 warp per n
    const int blocks = (N * 32 + threads - 1) / threads;
    neural_alu_add_kernel<<<blocks, threads>>>(a, b, out, N);
}